// round 17
// baseline (speedup 1.0000x reference)
#include <cuda_runtime.h>
#include <math.h>
#include <stdint.h>

#define Dm   768
#define Hh   12
#define HDm  64
#define DFFm 3072
#define Bb   2
#define Ss   4096
#define NT   (Bb*Ss)
#define DQKV (3*Dm)   // 2304

// ---- scratch ----
__device__ float g_h   [NT*Dm];
__device__ float g_qkv [NT*DQKV];
__device__ float g_ctx [NT*Dm];
__device__ float g_x1  [NT*Dm];
__device__ float g_h2  [NT*Dm];
__device__ float g_ff1 [NT*DFFm];
// transposed+rounded weights: Wqkv^T [2304][768], Wo^T [768][768], W1^T [3072][768], W2^T [768][3072]
__device__ float g_w   [Dm*DQKV + Dm*Dm + 2*Dm*DFFm];
__device__ float g_bqkv[DQKV];

// ---------- helpers ----------
__device__ __forceinline__ uint32_t f2tf32(float f) {
    uint32_t r;
    asm("cvt.rna.tf32.f32 %0, %1;" : "=r"(r) : "f"(f));
    return r;
}
__device__ __forceinline__ float rtf(float f) { return __uint_as_float(f2tf32(f)); }

__device__ __forceinline__ void cp_async16(void* smem, const void* gmem) {
    uint32_t s = (uint32_t)__cvta_generic_to_shared(smem);
    asm volatile("cp.async.cg.shared.global [%0], [%1], 16;" :: "r"(s), "l"(gmem));
}

__device__ __forceinline__ void ldsm_x4(uint32_t& r0, uint32_t& r1, uint32_t& r2, uint32_t& r3, uint32_t addr) {
    asm volatile("ldmatrix.sync.aligned.m8n8.x4.shared.b16 {%0,%1,%2,%3}, [%4];"
        : "=r"(r0), "=r"(r1), "=r"(r2), "=r"(r3) : "r"(addr));
}

// ============================ transpose + tf32-round pre-pass ============================
// src: [K][N] row-major -> dst: [N][K] row-major, values rounded to tf32(RNA).
__global__ void transpose_round_kernel(const float* __restrict__ src,
                                       float* __restrict__ dst, int K, int N) {
    __shared__ float t[32][33];
    int bx = blockIdx.x * 32;   // n base
    int by = blockIdx.y * 32;   // k base
    int x = threadIdx.x, y = threadIdx.y;   // 32x8
    #pragma unroll
    for (int j = 0; j < 32; j += 8)
        t[y + j][x] = src[(size_t)(by + y + j) * N + bx + x];
    __syncthreads();
    #pragma unroll
    for (int j = 0; j < 32; j += 8)
        dst[(size_t)(bx + y + j) * K + by + x] = rtf(t[x][y + j]);
}

__global__ void concat_bias_kernel(const float* __restrict__ bq,
                                   const float* __restrict__ bk,
                                   const float* __restrict__ bv,
                                   float* __restrict__ dst) {
    int i = blockIdx.x * blockDim.x + threadIdx.x;
    if (i < DQKV)
        dst[i] = (i < Dm) ? bq[i] : (i < 2 * Dm) ? bk[i - Dm] : bv[i - 2 * Dm];
}

// ============================ LayerNorm (tf32-rounded output) ============================
__global__ void ln_kernel(const float* __restrict__ x,
                          const float* __restrict__ g,
                          const float* __restrict__ b,
                          float* __restrict__ out) {
    int row = blockIdx.x;
    const float* xr = x + (size_t)row * Dm;
    int tid = threadIdx.x;
    float v0 = xr[tid], v1 = xr[tid + 256], v2 = xr[tid + 512];
    float s  = v0 + v1 + v2;
    float s2 = v0*v0 + v1*v1 + v2*v2;
    #pragma unroll
    for (int o = 16; o; o >>= 1) {
        s  += __shfl_xor_sync(0xffffffffu, s,  o);
        s2 += __shfl_xor_sync(0xffffffffu, s2, o);
    }
    __shared__ float ws[8], ws2[8];
    int w = tid >> 5, l = tid & 31;
    if (l == 0) { ws[w] = s; ws2[w] = s2; }
    __syncthreads();
    __shared__ float smu, srs;
    if (w == 0) {
        s  = (l < 8) ? ws[l]  : 0.f;
        s2 = (l < 8) ? ws2[l] : 0.f;
        #pragma unroll
        for (int o = 4; o; o >>= 1) {
            s  += __shfl_xor_sync(0xffffffffu, s,  o);
            s2 += __shfl_xor_sync(0xffffffffu, s2, o);
        }
        if (l == 0) {
            float mu  = s / Dm;
            float var = fmaxf(s2 / Dm - mu * mu, 0.f);
            smu = mu;
            srs = rsqrtf(var + 1e-5f);
        }
    }
    __syncthreads();
    float mu = smu, rs = srs;
    float* outr = out + (size_t)row * Dm;
    outr[tid]       = rtf((v0 - mu) * rs * g[tid]       + b[tid]);
    outr[tid + 256] = rtf((v1 - mu) * rs * g[tid + 256] + b[tid + 256]);
    outr[tid + 512] = rtf((v2 - mu) * rs * g[tid + 512] + b[tid + 512]);
}

// ============================ TF32 tensor-core GEMM (cp.async 2-stage, ldmatrix A+B) ============================
// B operand is pre-transposed weights Bt [N][K] (k contiguous) -> B-frags via paired ldsm.x4.
#define ASTR 36
#define A_WORDS (128 * ASTR)
#define B_WORDS (128 * ASTR)
#define GEMM_SMEM (2 * (A_WORDS + B_WORDS) * 4)

template<bool RELU, bool RES, bool RNDC>
__global__ __launch_bounds__(256, 2)
void tf32gemm_kernel(const float* __restrict__ A,
                     const float* __restrict__ Bt,   // [N][K]
                     const float* __restrict__ bias,
                     const float* __restrict__ res,
                     float* __restrict__ C,
                     int M, int N, int K) {
    extern __shared__ uint32_t sh[];
    uint32_t* AsBase = sh;
    uint32_t* BsBase = sh + 2 * A_WORDS;

    int tid  = threadIdx.x;
    int lane = tid & 31;
    int warp = tid >> 5;
    int warp_m = warp & 1;
    int warp_n = warp >> 1;
    int grp = lane >> 2;
    int thr = lane & 3;

    int row0 = blockIdx.y * 128;
    int col0 = blockIdx.x * 128;

    int aoff  = (warp_m * 64 + (lane & 15)) * ASTR + ((lane >> 4) << 2);
    // paired B-frag ldsm.x4: (rows n0 | kb), (rows n0 | kb+4), (rows n0+8 | kb), (rows n0+8 | kb+4)
    int boff4 = ((lane & 7) + ((lane >> 4) << 3)) * ASTR + (((lane >> 3) & 1) << 2);

    float c[4][4][4];
    #pragma unroll
    for (int mt = 0; mt < 4; mt++)
        #pragma unroll
        for (int nt = 0; nt < 4; nt++)
            #pragma unroll
            for (int i = 0; i < 4; i++) c[mt][nt][i] = 0.f;

    auto load_tile = [&](int k0, int stg) {
        uint32_t* Ad = AsBase + stg * A_WORDS;
        uint32_t* Bd = BsBase + stg * B_WORDS;
        #pragma unroll
        for (int it = 0; it < 4; it++) {
            int i = it * 256 + tid;
            int r = i >> 3, kc = (i & 7) * 4;
            cp_async16(&Ad[r * ASTR + kc], A + (size_t)(row0 + r) * K + k0 + kc);
        }
        #pragma unroll
        for (int it = 0; it < 4; it++) {
            int i = it * 256 + tid;
            int r = i >> 3, kc = (i & 7) * 4;
            cp_async16(&Bd[r * ASTR + kc], Bt + (size_t)(col0 + r) * K + k0 + kc);
        }
        asm volatile("cp.async.commit_group;" ::: "memory");
    };

    int NK = K >> 5;
    load_tile(0, 0);

    for (int i = 0; i < NK; i++) {
        if (i + 1 < NK) {
            load_tile((i + 1) << 5, (i + 1) & 1);
            asm volatile("cp.async.wait_group 1;" ::: "memory");
        } else {
            asm volatile("cp.async.wait_group 0;" ::: "memory");
        }
        __syncthreads();

        uint32_t asU = (uint32_t)__cvta_generic_to_shared(AsBase + (i & 1) * A_WORDS);
        uint32_t bsU = (uint32_t)__cvta_generic_to_shared(BsBase + (i & 1) * B_WORDS);

        #pragma unroll
        for (int ks = 0; ks < 4; ks++) {
            int kb = ks * 8;
            uint32_t af[4][4];
            #pragma unroll
            for (int mt = 0; mt < 4; mt++)
                ldsm_x4(af[mt][0], af[mt][1], af[mt][2], af[mt][3],
                        asU + (uint32_t)(aoff + mt * 16 * ASTR + kb) * 4u);
            uint32_t bf[4][2];
            #pragma unroll
            for (int p = 0; p < 2; p++) {
                int n0 = warp_n * 32 + p * 16;
                ldsm_x4(bf[p*2][0], bf[p*2][1], bf[p*2+1][0], bf[p*2+1][1],
                        bsU + (uint32_t)(boff4 + n0 * ASTR + kb) * 4u);
            }
            #pragma unroll
            for (int mt = 0; mt < 4; mt++)
                #pragma unroll
                for (int nt = 0; nt < 4; nt++) {
                    asm("mma.sync.aligned.m16n8k8.row.col.f32.tf32.tf32.f32 "
                        "{%0,%1,%2,%3}, {%4,%5,%6,%7}, {%8,%9}, {%0,%1,%2,%3};"
                        : "+f"(c[mt][nt][0]), "+f"(c[mt][nt][1]),
                          "+f"(c[mt][nt][2]), "+f"(c[mt][nt][3])
                        : "r"(af[mt][0]), "r"(af[mt][1]), "r"(af[mt][2]), "r"(af[mt][3]),
                          "r"(bf[nt][0]), "r"(bf[nt][1]));
                }
        }
        __syncthreads();
    }

    #pragma unroll
    for (int mt = 0; mt < 4; mt++) {
        int r = row0 + warp_m * 64 + mt * 16 + grp;
        #pragma unroll
        for (int nt = 0; nt < 4; nt++) {
            int cc = col0 + warp_n * 32 + nt * 8 + 2 * thr;
            float b0 = bias[cc], b1 = bias[cc + 1];
            float o0 = c[mt][nt][0] + b0, o1 = c[mt][nt][1] + b1;
            float o2 = c[mt][nt][2] + b0, o3 = c[mt][nt][3] + b1;
            if (RELU) {
                o0 = fmaxf(o0, 0.f); o1 = fmaxf(o1, 0.f);
                o2 = fmaxf(o2, 0.f); o3 = fmaxf(o3, 0.f);
            }
            if (RES) {
                const float* rp0 = res + (size_t)r * N + cc;
                const float* rp1 = res + (size_t)(r + 8) * N + cc;
                o0 += rp0[0]; o1 += rp0[1];
                o2 += rp1[0]; o3 += rp1[1];
            }
            if (RNDC) {
                o0 = rtf(o0); o1 = rtf(o1); o2 = rtf(o2); o3 = rtf(o3);
            }
            *(float2*)&C[(size_t)r * N + cc]       = make_float2(o0, o1);
            *(float2*)&C[(size_t)(r + 8) * N + cc] = make_float2(o2, o3);
        }
    }
}

// ============================ TF32 tensor-core flash attention (R16, unchanged) ============================
#define ATS 72
#define KV_WORDS (64 * ATS)

__global__ __launch_bounds__(128, 3)
void attn_tc_kernel(const float* __restrict__ QKV,
                    const int*   __restrict__ am,
                    float* __restrict__ O) {
    extern __shared__ uint32_t smx[];
    uint32_t* Ps = smx;                  // [64][ATS] (Q staging, then P)
    uint32_t* Ks = Ps + KV_WORDS;        // [64][ATS] single buffer
    uint32_t* Vs = Ks + KV_WORDS;        // [2][64][ATS]
    uint32_t* AmS = Vs + 2 * KV_WORDS;   // [2][64] ints

    int tid  = threadIdx.x;
    int warp = tid >> 5;
    int lane = tid & 31;
    int grp  = lane >> 2;
    int thr  = lane & 3;

    int qt = gridDim.x - 1 - blockIdx.x;
    int q0 = qt * 64;
    int h  = blockIdx.y;
    int b  = blockIdx.z;
    int r0 = warp * 16;

    uint32_t ksU = (uint32_t)__cvta_generic_to_shared(Ks);
    uint32_t psU = (uint32_t)__cvta_generic_to_shared(Ps);

    int aoff  = (r0 + (lane & 15)) * ATS + ((lane >> 4) << 2);
    int koff4 = ((lane & 7) + ((lane >> 4) << 3)) * ATS + (((lane >> 3) & 1) << 2);

    const float* Qbase = QKV + ((size_t)(b * Ss + q0)) * DQKV + h * HDm;
    const float* Kbase = QKV + ((size_t)b * Ss) * DQKV + Dm + h * HDm;
    const float* Vbase = QKV + ((size_t)b * Ss) * DQKV + 2 * Dm + h * HDm;
    const int*   amb   = am + b * Ss;

    int ktiles = qt + 1;

    auto fill_V = [&](int kt, int stg) {
        const float* Vb = Vbase + (size_t)(kt * 64) * DQKV;
        uint32_t* Vd = Vs + stg * KV_WORDS;
        #pragma unroll
        for (int it = 0; it < 8; it++) {
            int i = it * 128 + tid;
            int r = i >> 4, c = (i & 15) * 4;
            cp_async16(&Vd[r * ATS + c], Vb + (size_t)r * DQKV + c);
        }
        if (tid < 16)
            cp_async16(&AmS[stg * 64 + tid * 4], amb + kt * 64 + tid * 4);
        asm volatile("cp.async.commit_group;" ::: "memory");
    };
    auto fill_K = [&](int kt) {
        const float* Kb = Kbase + (size_t)(kt * 64) * DQKV;
        #pragma unroll
        for (int it = 0; it < 8; it++) {
            int i = it * 128 + tid;
            int r = i >> 4, c = (i & 15) * 4;
            cp_async16(&Ks[r * ATS + c], Kb + (size_t)r * DQKV + c);
        }
        asm volatile("cp.async.commit_group;" ::: "memory");
    };

    fill_V(0, 0);
    fill_K(0);

    const float QSCALE = 0.125f * 1.44269504f;
    for (int i = tid; i < 64 * 16; i += 128) {
        int r = i >> 4, c = (i & 15) * 4;
        float4 v = *(const float4*)(Qbase + (size_t)r * DQKV + c);
        uint4 t;
        t.x = f2tf32(v.x * QSCALE); t.y = f2tf32(v.y * QSCALE);
        t.z = f2tf32(v.z * QSCALE); t.w = f2tf32(v.w * QSCALE);
        *(uint4*)&Ps[r * ATS + c] = t;
    }
    __syncthreads();
    uint32_t qa[8][4];
    #pragma unroll
    for (int ks = 0; ks < 8; ks++)
        ldsm_x4(qa[ks][0], qa[ks][1], qa[ks][2], qa[ks][3],
                psU + (uint32_t)(aoff + ks * 8) * 4u);
    __syncthreads();

    float o[8][4];
    #pragma unroll
    for (int nc = 0; nc < 8; nc++)
        #pragma unroll
        for (int i = 0; i < 4; i++) o[nc][i] = 0.f;
    float m0 = -INFINITY, m1 = -INFINITY, l0 = 0.f, l1 = 0.f;

    int qg0 = q0 + r0 + grp;
    int qg1 = qg0 + 8;

    for (int kt = 0; kt < ktiles; kt++) {
        int k0 = kt * 64;
        asm volatile("cp.async.wait_group 0;" ::: "memory");
        __syncthreads();
        if (kt + 1 < ktiles) fill_V(kt + 1, (kt + 1) & 1);

        const uint32_t* VsCur = Vs + (kt & 1) * KV_WORDS;
        const int* amS = (const int*)(AmS + (kt & 1) * 64);

        float s[8][4];
        #pragma unroll
        for (int nc = 0; nc < 8; nc++)
            #pragma unroll
            for (int i = 0; i < 4; i++) s[nc][i] = 0.f;

        #pragma unroll
        for (int ks = 0; ks < 8; ks++) {
            int kb = ks * 8;
            #pragma unroll
            for (int p = 0; p < 4; p++) {
                uint32_t b0, b1, b2, b3;
                ldsm_x4(b0, b1, b2, b3, ksU + (uint32_t)(koff4 + p * 16 * ATS + kb) * 4u);
                asm("mma.sync.aligned.m16n8k8.row.col.f32.tf32.tf32.f32 "
                    "{%0,%1,%2,%3}, {%4,%5,%6,%7}, {%8,%9}, {%0,%1,%2,%3};"
                    : "+f"(s[p*2][0]), "+f"(s[p*2][1]), "+f"(s[p*2][2]), "+f"(s[p*2][3])
                    : "r"(qa[ks][0]), "r"(qa[ks][1]), "r"(qa[ks][2]), "r"(qa[ks][3]),
                      "r"(b0), "r"(b1));
                asm("mma.sync.aligned.m16n8k8.row.col.f32.tf32.tf32.f32 "
                    "{%0,%1,%2,%3}, {%4,%5,%6,%7}, {%8,%9}, {%0,%1,%2,%3};"
                    : "+f"(s[p*2+1][0]), "+f"(s[p*2+1][1]), "+f"(s[p*2+1][2]), "+f"(s[p*2+1][3])
                    : "r"(qa[ks][0]), "r"(qa[ks][1]), "r"(qa[ks][2]), "r"(qa[ks][3]),
                      "r"(b2), "r"(b3));
            }
        }
        __syncthreads();
        if (kt + 1 < ktiles) fill_K(kt + 1);

        #pragma unroll
        for (int nc = 0; nc < 8; nc++) {
            int cl = nc * 8 + 2 * thr;
            int ca = k0 + cl;
            int cb = ca + 1;
            bool va = (amS[cl] != 0), vb = (amS[cl + 1] != 0);
            if (!(ca <= qg0 && va)) s[nc][0] = -INFINITY;
            if (!(cb <= qg0 && vb)) s[nc][1] = -INFINITY;
            if (!(ca <= qg1 && va)) s[nc][2] = -INFINITY;
            if (!(cb <= qg1 && vb)) s[nc][3] = -INFINITY;
        }

        float t0 = -INFINITY, t1 = -INFINITY;
        #pragma unroll
        for (int nc = 0; nc < 8; nc++) {
            t0 = fmaxf(t0, fmaxf(s[nc][0], s[nc][1]));
            t1 = fmaxf(t1, fmaxf(s[nc][2], s[nc][3]));
        }
        t0 = fmaxf(t0, __shfl_xor_sync(0xffffffffu, t0, 1));
        t0 = fmaxf(t0, __shfl_xor_sync(0xffffffffu, t0, 2));
        t1 = fmaxf(t1, __shfl_xor_sync(0xffffffffu, t1, 1));
        t1 = fmaxf(t1, __shfl_xor_sync(0xffffffffu, t1, 2));

        float mn0 = fmaxf(m0, t0), mn1 = fmaxf(m1, t1);
        float al0 = (mn0 == -INFINITY) ? 1.f : exp2f(m0 - mn0);
        float al1 = (mn1 == -INFINITY) ? 1.f : exp2f(m1 - mn1);
        bool any0 = (mn0 != -INFINITY), any1 = (mn1 != -INFINITY);

        float ps0 = 0.f, ps1 = 0.f;
        #pragma unroll
        for (int nc = 0; nc < 8; nc++) {
            float p0 = any0 ? exp2f(s[nc][0] - mn0) : 0.f;
            float p1 = any0 ? exp2f(s[nc][1] - mn0) : 0.f;
            float p2 = any1 ? exp2f(s[nc][2] - mn1) : 0.f;
            float p3 = any1 ? exp2f(s[nc][3] - mn1) : 0.f;
            ps0 += p0 + p1;
            ps1 += p2 + p3;
            *(uint2*)&Ps[(r0 + grp) * ATS + nc * 8 + 2 * thr]     = make_uint2(__float_as_uint(p0), __float_as_uint(p1));
            *(uint2*)&Ps[(r0 + grp + 8) * ATS + nc * 8 + 2 * thr] = make_uint2(__float_as_uint(p2), __float_as_uint(p3));
        }
        ps0 += __shfl_xor_sync(0xffffffffu, ps0, 1);
        ps0 += __shfl_xor_sync(0xffffffffu, ps0, 2);
        ps1 += __shfl_xor_sync(0xffffffffu, ps1, 1);
        ps1 += __shfl_xor_sync(0xffffffffu, ps1, 2);

        l0 = l0 * al0 + ps0;
        l1 = l1 * al1 + ps1;
        m0 = mn0; m1 = mn1;

        #pragma unroll
        for (int nc = 0; nc < 8; nc++) {
            o[nc][0] *= al0; o[nc][1] *= al0;
            o[nc][2] *= al1; o[nc][3] *= al1;
        }
        __syncwarp();

        #pragma unroll
        for (int ks = 0; ks < 8; ks++) {
            int kb = ks * 8;
            uint32_t a0, a1, a2, a3;
            ldsm_x4(a0, a1, a2, a3, psU + (uint32_t)(aoff + kb) * 4u);
            #pragma unroll
            for (int nc = 0; nc < 8; nc++) {
                uint32_t b0 = VsCur[(kb + thr) * ATS + nc * 8 + grp];
                uint32_t b1 = VsCur[(kb + thr + 4) * ATS + nc * 8 + grp];
                asm("mma.sync.aligned.m16n8k8.row.col.f32.tf32.tf32.f32 "
                    "{%0,%1,%2,%3}, {%4,%5,%6,%7}, {%8,%9}, {%0,%1,%2,%3};"
                    : "+f"(o[nc][0]), "+f"(o[nc][1]), "+f"(o[nc][2]), "+f"(o[nc][3])
                    : "r"(a0), "r"(a1), "r"(a2), "r"(a3), "r"(b0), "r"(b1));
            }
        }
    }

    float rl0 = (l0 > 0.f) ? 1.f / l0 : 0.f;
    float rl1 = (l1 > 0.f) ? 1.f / l1 : 0.f;
    float* Ob = O + ((size_t)(b * Ss + q0)) * Dm + h * HDm;
    #pragma unroll
    for (int nc = 0; nc < 8; nc++) {
        int cc = nc * 8 + 2 * thr;
        *(float2*)(Ob + (size_t)(r0 + grp) * Dm + cc)     = make_float2(rtf(o[nc][0] * rl0), rtf(o[nc][1] * rl0));
        *(float2*)(Ob + (size_t)(r0 + grp + 8) * Dm + cc) = make_float2(rtf(o[nc][2] * rl1), rtf(o[nc][3] * rl1));
    }
}

// ============================ launch ============================
extern "C" void kernel_launch(void* const* d_in, const int* in_sizes, int n_in,
                              void* d_out, int out_size) {
    const float* x     = (const float*)d_in[0];
    const int*   am    = (const int*)  d_in[1];
    const float* ln1_g = (const float*)d_in[2];
    const float* ln1_b = (const float*)d_in[3];
    const float* ln2_g = (const float*)d_in[4];
    const float* ln2_b = (const float*)d_in[5];
    const float* Wq = (const float*)d_in[6];
    const float* bq = (const float*)d_in[7];
    const float* Wk = (const float*)d_in[8];
    const float* bk = (const float*)d_in[9];
    const float* Wv = (const float*)d_in[10];
    const float* bv = (const float*)d_in[11];
    const float* Wo = (const float*)d_in[12];
    const float* bo = (const float*)d_in[13];
    const float* W1 = (const float*)d_in[14];
    const float* b1 = (const float*)d_in[15];
    const float* W2 = (const float*)d_in[16];
    const float* b2 = (const float*)d_in[17];
    float* out = (float*)d_out;

    float *h, *qkv, *ctx, *x1, *h2, *ff1, *wbuf, *bqkv;
    cudaGetSymbolAddress((void**)&h,    g_h);
    cudaGetSymbolAddress((void**)&qkv,  g_qkv);
    cudaGetSymbolAddress((void**)&ctx,  g_ctx);
    cudaGetSymbolAddress((void**)&x1,   g_x1);
    cudaGetSymbolAddress((void**)&h2,   g_h2);
    cudaGetSymbolAddress((void**)&ff1,  g_ff1);
    cudaGetSymbolAddress((void**)&wbuf, g_w);
    cudaGetSymbolAddress((void**)&bqkv, g_bqkv);

    // transposed weight layouts: Wqkv^T [2304][768] (q rows 0..767, k rows 768.., v rows 1536..)
    float* tWqkv = wbuf;
    float* tWo   = tWqkv + Dm * DQKV;
    float* tW1   = tWo + Dm * Dm;        // [3072][768]
    float* tW2   = tW1 + Dm * DFFm;      // [768][3072]

    dim3 tb(32, 8);
    transpose_round_kernel<<<dim3(Dm / 32, Dm / 32), tb>>>(Wq, tWqkv,              Dm, Dm);
    transpose_round_kernel<<<dim3(Dm / 32, Dm / 32), tb>>>(Wk, tWqkv + Dm * Dm,    Dm, Dm);
    transpose_round_kernel<<<dim3(Dm / 32, Dm / 32), tb>>>(Wv, tWqkv + 2 * Dm * Dm, Dm, Dm);
    transpose_round_kernel<<<dim3(Dm / 32, Dm / 32), tb>>>(Wo, tWo, Dm, Dm);
    transpose_round_kernel<<<dim3(DFFm / 32, Dm / 32), tb>>>(W1, tW1, Dm, DFFm);
    transpose_round_kernel<<<dim3(Dm / 32, DFFm / 32), tb>>>(W2, tW2, DFFm, Dm);
    concat_bias_kernel<<<(DQKV + 255) / 256, 256>>>(bq, bk, bv, bqkv);

    cudaFuncSetAttribute(tf32gemm_kernel<false, false, false>, cudaFuncAttributeMaxDynamicSharedMemorySize, GEMM_SMEM);
    cudaFuncSetAttribute(tf32gemm_kernel<false, true,  false>, cudaFuncAttributeMaxDynamicSharedMemorySize, GEMM_SMEM);
    cudaFuncSetAttribute(tf32gemm_kernel<true,  false, true >, cudaFuncAttributeMaxDynamicSharedMemorySize, GEMM_SMEM);

    ln_kernel<<<NT, 256>>>(x, ln1_g, ln1_b, h);

    tf32gemm_kernel<false, false, false><<<dim3(DQKV / 128, NT / 128), 256, GEMM_SMEM>>>(h, tWqkv, bqkv, nullptr, qkv, NT, DQKV, Dm);

    const int ATTN_SMEM = 4 * 64 * ATS * 4 + 2 * 64 * 4;
    cudaFuncSetAttribute(attn_tc_kernel, cudaFuncAttributeMaxDynamicSharedMemorySize, ATTN_SMEM);
    attn_tc_kernel<<<dim3(Ss / 64, Hh, Bb), 128, ATTN_SMEM>>>(qkv, am, ctx);

    dim3 gD(Dm / 128, NT / 128);
    tf32gemm_kernel<false, true, false><<<gD, 256, GEMM_SMEM>>>(ctx, tWo, bo, x, x1, NT, Dm, Dm);

    ln_kernel<<<NT, 256>>>(x1, ln2_g, ln2_b, h2);

    tf32gemm_kernel<true, false, true><<<dim3(DFFm / 128, NT / 128), 256, GEMM_SMEM>>>(h2, tW1, b1, nullptr, ff1, NT, DFFm, Dm);
    tf32gemm_kernel<false, true, false><<<gD, 256, GEMM_SMEM>>>(ff1, tW2, b2, x1, out, NT, Dm, DFFm);
}